// round 2
// baseline (speedup 1.0000x reference)
#include <cuda_runtime.h>
#include <math.h>

#define Tn    2048
#define HIDn  2048
#define Hn    32
#define HKVn  2
#define Dn    64
#define Gn    2
#define HGn   16
#define BLKn  32
#define NSELn 8
#define WINn  256
#define NBn   64
#define OUTDn 2400
#define KOFF  (Hn*Dn)            /* 2048 */
#define VOFF  (KOFF + HKVn*Dn)   /* 2176 */
#define WOFF  (VOFF + HKVn*Dn)   /* 2304 */
#define NEGf  (-1e30f)
#define SCALEf 0.125f

// ---------------- scratch (device globals; no allocation allowed) ----------------
__device__ float g_qkvw[Tn*OUTDn];        // projected qkvw
__device__ float g_q[Tn*Hn*Dn];           // rope'd q
__device__ float g_k[Tn*HKVn*Dn];         // rope'd k
__device__ float g_kcmp[NBn*Gn*Dn];
__device__ float g_vcmp[NBn*Gn*Dn];
__device__ float g_pcmp[Tn*Hn*NBn];
__device__ float g_ocmp[Tn*Hn*Dn];
__device__ float g_osel[Tn*Hn*Dn];
__device__ float g_owin[Tn*Hn*Dn];
__device__ int   g_selidx[Tn*Gn*NSELn];
__device__ float g_o[Tn*Hn*Dn];           // gated combined output (T x 2048)

// ---------------- warp reduce helpers ----------------
__device__ __forceinline__ float warpMax(float v) {
    #pragma unroll
    for (int o = 16; o > 0; o >>= 1) v = fmaxf(v, __shfl_xor_sync(0xffffffffu, v, o));
    return v;
}
__device__ __forceinline__ float warpSum(float v) {
    #pragma unroll
    for (int o = 16; o > 0; o >>= 1) v += __shfl_xor_sync(0xffffffffu, v, o);
    return v;
}

// ---------------- GEMM body: C[M,N] = A[M,K] @ B[K,N], fp32, 128x128x8 tile ----------------
// M % 128 == 0, K % 8 == 0 assumed. N guarded (N % 4 == 0).
__device__ __forceinline__ void gemm_body(const float* __restrict__ A,
                                          const float* __restrict__ B,
                                          float* __restrict__ C,
                                          int M, int N, int K) {
    __shared__ float As[8][128];
    __shared__ float Bs[8][128];
    const int tid  = threadIdx.x;
    const int brow = blockIdx.y * 128;
    const int bcol = blockIdx.x * 128;
    const int tr = (tid >> 4) << 3;   // row offset of 8x8 microtile
    const int tc = (tid & 15) << 3;   // col offset

    float acc[8][8];
    #pragma unroll
    for (int i = 0; i < 8; i++)
        #pragma unroll
        for (int j = 0; j < 8; j++) acc[i][j] = 0.f;

    const int a_row = tid >> 1;          // 0..127
    const int a_col = (tid & 1) << 2;    // 0 or 4
    const int b_row = tid >> 5;          // 0..7
    const int b_col = (tid & 31) << 2;   // 0..124

    const float* Aptr = A + (size_t)(brow + a_row) * K + a_col;
    const float* Bptr = B + (size_t)b_row * N + bcol + b_col;
    const bool bok = (bcol + b_col) < N;

    for (int k0 = 0; k0 < K; k0 += 8) {
        float4 av = *(const float4*)Aptr;
        Aptr += 8;
        As[a_col + 0][a_row] = av.x;
        As[a_col + 1][a_row] = av.y;
        As[a_col + 2][a_row] = av.z;
        As[a_col + 3][a_row] = av.w;

        float4 bv = make_float4(0.f, 0.f, 0.f, 0.f);
        if (bok) bv = *(const float4*)Bptr;
        Bptr += (size_t)8 * N;
        *(float4*)&Bs[b_row][b_col] = bv;

        __syncthreads();
        #pragma unroll
        for (int kk = 0; kk < 8; kk++) {
            float ar[8], br[8];
            #pragma unroll
            for (int i = 0; i < 8; i++) ar[i] = As[kk][tr + i];
            #pragma unroll
            for (int j = 0; j < 8; j++) br[j] = Bs[kk][tc + j];
            #pragma unroll
            for (int i = 0; i < 8; i++)
                #pragma unroll
                for (int j = 0; j < 8; j++) acc[i][j] = fmaf(ar[i], br[j], acc[i][j]);
        }
        __syncthreads();
    }

    #pragma unroll
    for (int i = 0; i < 8; i++) {
        const int row = brow + tr + i;
        #pragma unroll
        for (int j = 0; j < 8; j++) {
            const int col = bcol + tc + j;
            if (col < N) C[(size_t)row * N + col] = acc[i][j];
        }
    }
}

// qkvw = x @ Wqkv  (scratch output resolved in device code; no host symbol lookup)
__global__ __launch_bounds__(256, 2) void gemm_qkvw(const float* __restrict__ A,
                                                    const float* __restrict__ B) {
    gemm_body(A, B, g_qkvw, Tn, OUTDn, HIDn);
}

// out = g_o @ Wo
__global__ __launch_bounds__(256, 2) void gemm_out(const float* __restrict__ B,
                                                   float* __restrict__ C) {
    gemm_body(g_o, B, C, Tn, HIDn, HIDn);
}

// ---------------- RoPE + split: write rope'd q and k ----------------
__global__ void rope_kernel(const float* __restrict__ cosp, const float* __restrict__ sinp) {
    int idx = blockIdx.x * blockDim.x + threadIdx.x;
    const int total = Tn * (Hn + HKVn) * Dn;
    if (idx >= total) return;
    const int d = idx & 63;
    int rest = idx >> 6;
    const int h = rest % (Hn + HKVn);
    const int t = rest / (Hn + HKVn);
    const float c = cosp[t * Dn + d];
    const float s = sinp[t * Dn + d];
    if (h < Hn) {
        const float* row = g_qkvw + (size_t)t * OUTDn + h * Dn;
        float x = row[d];
        float rot = (d < 32) ? -row[d + 32] : row[d - 32];
        g_q[((size_t)t * Hn + h) * Dn + d] = x * c + rot * s;
    } else {
        const int g = h - Hn;
        const float* row = g_qkvw + (size_t)t * OUTDn + KOFF + g * Dn;
        float x = row[d];
        float rot = (d < 32) ? -row[d + 32] : row[d - 32];
        g_k[((size_t)t * HKVn + g) * Dn + d] = x * c + rot * s;
    }
}

// ---------------- mean-pool compressed K/V ----------------
__global__ void pool_kernel() {
    int idx = blockIdx.x * blockDim.x + threadIdx.x;
    const int total = NBn * Gn * Dn;
    if (idx >= total) return;
    const int d = idx & 63;
    int rest = idx >> 6;
    const int g = rest % Gn;
    const int n = rest / Gn;
    float sk = 0.f, sv = 0.f;
    #pragma unroll 4
    for (int b = 0; b < BLKn; b++) {
        const int t = n * BLKn + b;
        sk += g_k[((size_t)t * HKVn + g) * Dn + d];
        sv += g_qkvw[(size_t)t * OUTDn + VOFF + g * Dn + d];
    }
    g_kcmp[idx] = sk * (1.f / BLKn);
    g_vcmp[idx] = sv * (1.f / BLKn);
}

// ---------------- compressed attention: one warp per (t, h) ----------------
__global__ __launch_bounds__(256) void cmp_kernel() {
    const int warp = (blockIdx.x * blockDim.x + threadIdx.x) >> 5;
    const int lane = threadIdx.x & 31;
    const int wl = threadIdx.x >> 5;
    const int t = warp / Hn;
    const int h = warp % Hn;
    const int g = h / HGn;

    __shared__ float qs[8][Dn];
    __shared__ float ps[8][NBn];

    const float* qrow = g_q + ((size_t)t * Hn + h) * Dn;
    qs[wl][lane]      = qrow[lane];
    qs[wl][lane + 32] = qrow[lane + 32];
    __syncwarp();

    const int nvis = (t + 1) >> 5;   // blocks fully ended by t
    float sc[2];
    #pragma unroll
    for (int i = 0; i < 2; i++) {
        const int n = lane + i * 32;
        float s = NEGf;
        if (n < nvis) {
            const float4* kr = (const float4*)(g_kcmp + ((size_t)n * Gn + g) * Dn);
            float acc = 0.f;
            #pragma unroll
            for (int d4 = 0; d4 < 16; d4++) {
                float4 kv = kr[d4];
                acc += kv.x * qs[wl][4*d4+0] + kv.y * qs[wl][4*d4+1]
                     + kv.z * qs[wl][4*d4+2] + kv.w * qs[wl][4*d4+3];
            }
            s = acc * SCALEf;
        }
        sc[i] = s;
    }

    float p0 = 0.f, p1 = 0.f;
    if (nvis > 0) {
        float m = warpMax(fmaxf(sc[0], sc[1]));
        float e0 = expf(sc[0] - m);
        float e1 = expf(sc[1] - m);
        float ssum = warpSum(e0 + e1);
        float inv = 1.f / ssum;
        p0 = e0 * inv; p1 = e1 * inv;
    }
    ps[wl][lane]      = p0;
    ps[wl][lane + 32] = p1;
    float* pout = g_pcmp + ((size_t)t * Hn + h) * NBn;
    pout[lane]      = p0;
    pout[lane + 32] = p1;
    __syncwarp();

    float acc0 = 0.f, acc1 = 0.f;
    for (int n = 0; n < nvis; n++) {
        const float p = ps[wl][n];
        const float* vr = g_vcmp + ((size_t)n * Gn + g) * Dn;
        acc0 += p * vr[lane];
        acc1 += p * vr[lane + 32];
    }
    float* orow = g_ocmp + ((size_t)t * Hn + h) * Dn;
    orow[lane]      = acc0;
    orow[lane + 32] = acc1;
}

// ---------------- importance + top-8 selection: one thread per (t, g) ----------------
__global__ void topk_kernel() {
    int idx = blockIdx.x * blockDim.x + threadIdx.x;
    if (idx >= Tn * Gn) return;
    const int g = idx % Gn;
    const int t = idx / Gn;
    const int tb = t >> 5;
    float imp[NBn];
    for (int n = 0; n < NBn; n++) {
        if (n > tb) { imp[n] = NEGf; continue; }
        float s = 0.f;
        #pragma unroll
        for (int hg = 0; hg < HGn; hg++)
            s += g_pcmp[((size_t)t * Hn + g * HGn + hg) * NBn + n];
        if (n == 0)  s += 1e4f;
        if (n == tb) s += 1e4f;
        imp[n] = s;
    }
    int* sel = g_selidx + ((size_t)t * Gn + g) * NSELn;
    for (int i = 0; i < NSELn; i++) {
        int best = 0; float bv = imp[0];
        for (int n = 1; n < NBn; n++)
            if (imp[n] > bv) { bv = imp[n]; best = n; }   // strict > : lowest index on ties
        sel[i] = best;
        imp[best] = -2e30f;
    }
}

// ---------------- selection attention: one warp per (t, h) ----------------
__global__ __launch_bounds__(256) void sel_kernel() {
    const int warp = (blockIdx.x * blockDim.x + threadIdx.x) >> 5;
    const int lane = threadIdx.x & 31;
    const int wl = threadIdx.x >> 5;
    const int t = warp / Hn;
    const int h = warp % Hn;
    const int g = h / HGn;

    __shared__ float qs[8][Dn];
    __shared__ float ps[8][NSELn * BLKn];
    __shared__ int   sb[8][NSELn];

    const float* qrow = g_q + ((size_t)t * Hn + h) * Dn;
    qs[wl][lane]      = qrow[lane];
    qs[wl][lane + 32] = qrow[lane + 32];
    if (lane < NSELn) sb[wl][lane] = g_selidx[((size_t)t * Gn + g) * NSELn + lane];
    __syncwarp();

    float sc[NSELn];
    #pragma unroll
    for (int i = 0; i < NSELn; i++) {
        const int pos = sb[wl][i] * BLKn + lane;
        float s = NEGf;
        if (pos <= t) {
            const float4* kr = (const float4*)(g_k + ((size_t)pos * HKVn + g) * Dn);
            float acc = 0.f;
            #pragma unroll
            for (int d4 = 0; d4 < 16; d4++) {
                float4 kv = kr[d4];
                acc += kv.x * qs[wl][4*d4+0] + kv.y * qs[wl][4*d4+1]
                     + kv.z * qs[wl][4*d4+2] + kv.w * qs[wl][4*d4+3];
            }
            s = acc * SCALEf;
        }
        sc[i] = s;
    }
    float lm = sc[0];
    #pragma unroll
    for (int i = 1; i < NSELn; i++) lm = fmaxf(lm, sc[i]);
    float m = warpMax(lm);
    float lsum = 0.f;
    float ev[NSELn];
    #pragma unroll
    for (int i = 0; i < NSELn; i++) { ev[i] = expf(sc[i] - m); lsum += ev[i]; }
    float ssum = warpSum(lsum);
    float inv = 1.f / ssum;
    #pragma unroll
    for (int i = 0; i < NSELn; i++) ps[wl][i * 32 + lane] = ev[i] * inv;
    __syncwarp();

    float acc0 = 0.f, acc1 = 0.f;
    #pragma unroll
    for (int i = 0; i < NSELn; i++) {
        const int base = sb[wl][i] * BLKn;
        if (base > t) continue;   // fully masked block, zero mass
        for (int b = 0; b < BLKn; b++) {
            const float p = ps[wl][i * 32 + b];
            const float* vr = g_qkvw + (size_t)(base + b) * OUTDn + VOFF + g * Dn;
            acc0 += p * vr[lane];
            acc1 += p * vr[lane + 32];
        }
    }
    float* orow = g_osel + ((size_t)t * Hn + h) * Dn;
    orow[lane]      = acc0;
    orow[lane + 32] = acc1;
}

// ---------------- sliding-window attention: one warp per (t, h) ----------------
__global__ __launch_bounds__(256) void win_kernel() {
    const int warp = (blockIdx.x * blockDim.x + threadIdx.x) >> 5;
    const int lane = threadIdx.x & 31;
    const int wl = threadIdx.x >> 5;
    const int t = warp / Hn;
    const int h = warp % Hn;
    const int g = h / HGn;

    __shared__ float qs[8][Dn];
    __shared__ float ps[8][WINn];

    const float* qrow = g_q + ((size_t)t * Hn + h) * Dn;
    qs[wl][lane]      = qrow[lane];
    qs[wl][lane + 32] = qrow[lane + 32];
    __syncwarp();

    const int p0 = t - (WINn - 1);
    float sc[8];
    #pragma unroll
    for (int i = 0; i < 8; i++) {
        const int pos = p0 + i * 32 + lane;
        float s = NEGf;
        if (pos >= 0) {
            const float4* kr = (const float4*)(g_k + ((size_t)pos * HKVn + g) * Dn);
            float acc = 0.f;
            #pragma unroll
            for (int d4 = 0; d4 < 16; d4++) {
                float4 kv = kr[d4];
                acc += kv.x * qs[wl][4*d4+0] + kv.y * qs[wl][4*d4+1]
                     + kv.z * qs[wl][4*d4+2] + kv.w * qs[wl][4*d4+3];
            }
            s = acc * SCALEf;
        }
        sc[i] = s;
    }
    float lm = sc[0];
    #pragma unroll
    for (int i = 1; i < 8; i++) lm = fmaxf(lm, sc[i]);
    float m = warpMax(lm);
    float lsum = 0.f;
    float ev[8];
    #pragma unroll
    for (int i = 0; i < 8; i++) { ev[i] = expf(sc[i] - m); lsum += ev[i]; }
    float ssum = warpSum(lsum);
    float inv = 1.f / ssum;
    #pragma unroll
    for (int i = 0; i < 8; i++) ps[wl][i * 32 + lane] = ev[i] * inv;
    __syncwarp();

    float acc0 = 0.f, acc1 = 0.f;
    const int j0 = (p0 < 0) ? -p0 : 0;
    for (int j = j0; j < WINn; j++) {
        const float p = ps[wl][j];
        const int pos = p0 + j;
        const float* vr = g_qkvw + (size_t)pos * OUTDn + VOFF + g * Dn;
        acc0 += p * vr[lane];
        acc1 += p * vr[lane + 32];
    }
    float* orow = g_owin + ((size_t)t * Hn + h) * Dn;
    orow[lane]      = acc0;
    orow[lane + 32] = acc1;
}

// ---------------- gated combine ----------------
__global__ void combine_kernel() {
    int idx = blockIdx.x * blockDim.x + threadIdx.x;
    const int total = Tn * Hn * Dn;
    if (idx >= total) return;
    const int d = idx & 63;
    int rest = idx >> 6;
    const int h = rest % Hn;
    const int t = rest / Hn;
    const float* wrow = g_qkvw + (size_t)t * OUTDn + WOFF + h * 3;
    const float g0 = 1.f / (1.f + expf(-wrow[0]));
    const float g1 = 1.f / (1.f + expf(-wrow[1]));
    const float g2 = 1.f / (1.f + expf(-wrow[2]));
    g_o[idx] = g0 * g_ocmp[idx] + g1 * g_osel[idx] + g2 * g_owin[idx];
}

// ---------------- launch ----------------
extern "C" void kernel_launch(void* const* d_in, const int* in_sizes, int n_in,
                              void* d_out, int out_size) {
    const float* x     = (const float*)d_in[0];  // [T, 1, HID]
    const float* cosp  = (const float*)d_in[1];  // [T, 64]
    const float* sinp  = (const float*)d_in[2];  // [T, 64]
    const float* Wqkv  = (const float*)d_in[3];  // [HID, OUTD]
    const float* Wo    = (const float*)d_in[4];  // [H*DV, HID]
    float* out = (float*)d_out;

    // 1. qkvw projection
    {
        dim3 grid((OUTDn + 127) / 128, Tn / 128);
        gemm_qkvw<<<grid, 256>>>(x, Wqkv);
    }
    // 2. rope
    {
        const int tot = Tn * (Hn + HKVn) * Dn;
        rope_kernel<<<(tot + 255) / 256, 256>>>(cosp, sinp);
    }
    // 3. compressed pooling
    {
        const int tot = NBn * Gn * Dn;
        pool_kernel<<<(tot + 255) / 256, 256>>>();
    }
    // 4. compressed attention
    cmp_kernel<<<Tn * Hn / 8, 256>>>();
    // 5. top-k selection
    topk_kernel<<<(Tn * Gn + 255) / 256, 256>>>();
    // 6. selection attention
    sel_kernel<<<Tn * Hn / 8, 256>>>();
    // 7. window attention
    win_kernel<<<Tn * Hn / 8, 256>>>();
    // 8. gated combine
    {
        const int tot = Tn * Hn * Dn;
        combine_kernel<<<(tot + 255) / 256, 256>>>();
    }
    // 9. output projection
    {
        dim3 grid(HIDn / 128, Tn / 128);
        gemm_out<<<grid, 256>>>(Wo, out);
    }
}

// round 5
// speedup vs baseline: 2.1153x; 2.1153x over previous
#include <cuda_runtime.h>
#include <cuda_bf16.h>
#include <cstdint>
#include <math.h>

#define Tn    2048
#define HIDn  2048
#define Hn    32
#define HKVn  2
#define Dn    64
#define Gn    2
#define HGn   16
#define BLKn  32
#define NSELn 8
#define WINn  256
#define NBn   64
#define OUTDn 2400
#define NPADn 2432          /* 19*128 */
#define K2n   8192          /* 4x K=2048 interleaved hi/lo */
#define KOFF  (Hn*Dn)
#define VOFF  (KOFF + HKVn*Dn)
#define WOFF  (VOFF + HKVn*Dn)
#define NEGf  (-1e30f)
#define SCALEf 0.125f

// ---------------- scratch ----------------
__device__ float g_qkvw[Tn*OUTDn];
__device__ float g_q[Tn*Hn*Dn];
__device__ float g_k[Tn*HKVn*Dn];
__device__ float g_kcmp[NBn*Gn*Dn];
__device__ float g_vcmp[NBn*Gn*Dn];
__device__ float g_pcmp[Tn*Hn*NBn];
__device__ float g_ocmp[Tn*Hn*Dn];
__device__ float g_osel[Tn*Hn*Dn];
__device__ float g_owin[Tn*Hn*Dn];
__device__ int   g_selidx[Tn*Gn*NSELn];
__device__ __align__(16) __nv_bfloat16 g_a2x[(size_t)Tn*K2n];
__device__ __align__(16) __nv_bfloat16 g_a2o[(size_t)Tn*K2n];
__device__ __align__(16) __nv_bfloat16 g_b2q[(size_t)NPADn*K2n];
__device__ __align__(16) __nv_bfloat16 g_b2o[(size_t)HIDn*K2n];

// ---------------- helpers ----------------
__device__ __forceinline__ uint32_t smem_u32(const void* p) {
    uint32_t a;
    asm("{ .reg .u64 t; cvta.to.shared.u64 t, %1; cvt.u32.u64 %0, t; }" : "=r"(a) : "l"(p));
    return a;
}
#define CP_ASYNC16(dst, src) \
    asm volatile("cp.async.cg.shared.global [%0], [%1], 16;" :: "r"(dst), "l"(src) : "memory")
#define CP_COMMIT() asm volatile("cp.async.commit_group;" ::: "memory")
#define CP_WAIT0()  asm volatile("cp.async.wait_group 0;" ::: "memory")
#define CP_WAIT1()  asm volatile("cp.async.wait_group 1;" ::: "memory")

__device__ __forceinline__ void ldsm4(uint32_t &r0, uint32_t &r1, uint32_t &r2, uint32_t &r3,
                                      uint32_t addr) {
    asm volatile("ldmatrix.sync.aligned.m8n8.x4.shared.b16 {%0,%1,%2,%3}, [%4];"
                 : "=r"(r0), "=r"(r1), "=r"(r2), "=r"(r3) : "r"(addr));
}
__device__ __forceinline__ void mma_bf16(float* c, uint32_t a0, uint32_t a1, uint32_t a2,
                                         uint32_t a3, uint32_t b0, uint32_t b1) {
    asm volatile("mma.sync.aligned.m16n8k16.row.col.f32.bf16.bf16.f32 "
                 "{%0,%1,%2,%3}, {%4,%5,%6,%7}, {%8,%9}, {%0,%1,%2,%3};"
                 : "+f"(c[0]), "+f"(c[1]), "+f"(c[2]), "+f"(c[3])
                 : "r"(a0), "r"(a1), "r"(a2), "r"(a3), "r"(b0), "r"(b1));
}

__device__ __forceinline__ float warpMax(float v) {
    #pragma unroll
    for (int o = 16; o > 0; o >>= 1) v = fmaxf(v, __shfl_xor_sync(0xffffffffu, v, o));
    return v;
}
__device__ __forceinline__ float warpSum(float v) {
    #pragma unroll
    for (int o = 16; o > 0; o >>= 1) v += __shfl_xor_sync(0xffffffffu, v, o);
    return v;
}
__device__ __forceinline__ void f32_hl(float v, unsigned short &h, unsigned short &l) {
    __nv_bfloat16 bh = __float2bfloat16(v);
    float r = v - __bfloat162float(bh);
    __nv_bfloat16 bl = __float2bfloat16(r);
    h = __bfloat16_as_ushort(bh);
    l = __bfloat16_as_ushort(bl);
}

// ---------------- mma.sync split-bf16 GEMM body ----------------
// C[M,N] = A2[M,K2] @ B2[N,K2]^T ; CTA tile 128x128, K chunk 32, double-buffered cp.async.
#define SAst 40                      /* smem row stride in bf16 elems (80 B) */
#define STAGE_BYTES (128*SAst*2)     /* 10240 per operand */
__device__ __forceinline__ void gemm_body(const __nv_bfloat16* __restrict__ A2,
                                          const __nv_bfloat16* __restrict__ B2,
                                          float* __restrict__ C,
                                          int Nvalid, int ldc) {
    __shared__ __align__(16) unsigned char smem[4 * STAGE_BYTES];   // 40 KB
    const uint32_t sbase = smem_u32(smem);
    const int tid = threadIdx.x;
    const int lane = tid & 31;
    const int warp = tid >> 5;
    const int wm = warp >> 2;        // 0..1
    const int wn = warp & 3;         // 0..3
    const int m0 = blockIdx.y * 128;
    const int n0 = blockIdx.x * 128;

    const int lrow = tid >> 2;
    const int lk   = (tid & 3) * 8;
    const __nv_bfloat16* aG = A2 + (size_t)(m0 + lrow) * K2n + lk;
    const __nv_bfloat16* bG = B2 + (size_t)(n0 + lrow) * K2n + lk;
    const uint32_t wA0 = (uint32_t)(lrow * SAst + lk) * 2;
    const uint32_t wA1 = (uint32_t)((lrow + 64) * SAst + lk) * 2;

    float acc[4][4][4];
    #pragma unroll
    for (int i = 0; i < 4; i++)
        #pragma unroll
        for (int j = 0; j < 4; j++)
            #pragma unroll
            for (int r = 0; r < 4; r++) acc[i][j][r] = 0.f;

    const int NK = K2n / 32;

    const uint32_t aRow = (uint32_t)(wm * 64 + (lane & 15));
    const uint32_t aColSel = (uint32_t)((lane >> 4) * 8);
    const int ro = lane >> 3;
    const uint32_t bRow = (uint32_t)(wn * 32 + ((ro & 2) ? 8 : 0) + (lane & 7));
    const uint32_t bColSel = (uint32_t)((ro & 1) ? 8 : 0);

    {
        uint32_t sA = sbase;
        uint32_t sB = sbase + STAGE_BYTES;
        CP_ASYNC16(sA + wA0, aG);
        CP_ASYNC16(sA + wA1, aG + (size_t)64 * K2n);
        CP_ASYNC16(sB + wA0, bG);
        CP_ASYNC16(sB + wA1, bG + (size_t)64 * K2n);
        CP_COMMIT();
    }

    for (int kc = 0; kc < NK; kc++) {
        const int nxt = kc + 1;
        if (nxt < NK) {
            uint32_t st = (uint32_t)(nxt & 1) * (2 * STAGE_BYTES);
            uint32_t sA = sbase + st;
            uint32_t sB = sA + STAGE_BYTES;
            const __nv_bfloat16* ag = aG + (size_t)nxt * 32;
            const __nv_bfloat16* bg = bG + (size_t)nxt * 32;
            CP_ASYNC16(sA + wA0, ag);
            CP_ASYNC16(sA + wA1, ag + (size_t)64 * K2n);
            CP_ASYNC16(sB + wA0, bg);
            CP_ASYNC16(sB + wA1, bg + (size_t)64 * K2n);
            CP_COMMIT();
            CP_WAIT1();
        } else {
            CP_WAIT0();
        }
        __syncthreads();

        uint32_t st = (uint32_t)(kc & 1) * (2 * STAGE_BYTES);
        uint32_t sA = sbase + st;
        uint32_t sB = sA + STAGE_BYTES;

        #pragma unroll
        for (int s = 0; s < 2; s++) {
            uint32_t af[4][4];
            #pragma unroll
            for (int i = 0; i < 4; i++) {
                uint32_t addr = sA + ((aRow + i * 16) * SAst + s * 16 + aColSel) * 2;
                ldsm4(af[i][0], af[i][1], af[i][2], af[i][3], addr);
            }
            uint32_t bf[4][2];
            #pragma unroll
            for (int j2 = 0; j2 < 2; j2++) {
                uint32_t addr = sB + ((bRow + j2 * 16) * SAst + s * 16 + bColSel) * 2;
                uint32_t r0, r1, r2, r3;
                ldsm4(r0, r1, r2, r3, addr);
                bf[2*j2][0] = r0; bf[2*j2][1] = r1;
                bf[2*j2+1][0] = r2; bf[2*j2+1][1] = r3;
            }
            #pragma unroll
            for (int i = 0; i < 4; i++)
                #pragma unroll
                for (int j = 0; j < 4; j++)
                    mma_bf16(acc[i][j], af[i][0], af[i][1], af[i][2], af[i][3],
                             bf[j][0], bf[j][1]);
        }
        __syncthreads();
    }

    const int rbase = m0 + wm * 64 + (lane >> 2);
    const int cbase = n0 + wn * 32 + (lane & 3) * 2;
    #pragma unroll
    for (int i = 0; i < 4; i++) {
        #pragma unroll
        for (int j = 0; j < 4; j++) {
            int rr = rbase + i * 16;
            int cc = cbase + j * 8;
            if (cc < Nvalid) {
                float* p0 = C + (size_t)rr * ldc + cc;
                p0[0] = acc[i][j][0];
                if (cc + 1 < Nvalid) p0[1] = acc[i][j][1];
                float* p1 = C + (size_t)(rr + 8) * ldc + cc;
                p1[0] = acc[i][j][2];
                if (cc + 1 < Nvalid) p1[1] = acc[i][j][3];
            }
        }
    }
}

// wrappers: all scratch resolved in device code (no cudaGetSymbolAddress on host)
__global__ __launch_bounds__(256) void gemm_mma_qkvw() {
    gemm_body(g_a2x, g_b2q, g_qkvw, OUTDn, OUTDn);
}
__global__ __launch_bounds__(256) void gemm_mma_out(float* __restrict__ C) {
    gemm_body(g_a2o, g_b2o, C, HIDn, HIDn);
}

// ---------------- conversions ----------------
__global__ void conv_x_kernel(const float* __restrict__ x) {
    int idx = blockIdx.x * blockDim.x + threadIdx.x;
    if (idx >= Tn * HIDn) return;
    unsigned short h, l;
    f32_hl(x[idx], h, l);
    uint2 pk;
    pk.x = (uint32_t)h | ((uint32_t)h << 16);
    pk.y = (uint32_t)l | ((uint32_t)l << 16);
    *(uint2*)((char*)g_a2x + (size_t)idx * 8) = pk;
}
__device__ __forceinline__ void tr_body(const float* __restrict__ W,
                                        __nv_bfloat16* __restrict__ B2,
                                        int Ncols, int Npad) {
    __shared__ float tile[32][33];
    int n = blockIdx.x * 32 + threadIdx.x;
    int k = blockIdx.y * 32 + threadIdx.y;
    tile[threadIdx.y][threadIdx.x] = (n < Ncols) ? W[(size_t)k * Ncols + n] : 0.f;
    __syncthreads();
    int nn = blockIdx.x * 32 + threadIdx.y;
    int kk = blockIdx.y * 32 + threadIdx.x;
    if (nn < Npad) {
        unsigned short h, l;
        f32_hl(tile[threadIdx.x][threadIdx.y], h, l);
        uint2 pk;
        pk.x = (uint32_t)h | ((uint32_t)l << 16);
        pk.y = pk.x;
        *(uint2*)((char*)B2 + (size_t)nn * (K2n * 2) + (size_t)kk * 8) = pk;
    }
}
__global__ void tr_q_kernel(const float* __restrict__ W) { tr_body(W, g_b2q, OUTDn, NPADn); }
__global__ void tr_o_kernel(const float* __restrict__ W) { tr_body(W, g_b2o, HIDn, HIDn); }

// ---------------- RoPE ----------------
__global__ void rope_kernel(const float* __restrict__ cosp, const float* __restrict__ sinp) {
    int idx = blockIdx.x * blockDim.x + threadIdx.x;
    const int total = Tn * (Hn + HKVn) * Dn;
    if (idx >= total) return;
    const int d = idx & 63;
    int rest = idx >> 6;
    const int h = rest % (Hn + HKVn);
    const int t = rest / (Hn + HKVn);
    const float c = cosp[t * Dn + d];
    const float s = sinp[t * Dn + d];
    if (h < Hn) {
        const float* row = g_qkvw + (size_t)t * OUTDn + h * Dn;
        float x = row[d];
        float rot = (d < 32) ? -row[d + 32] : row[d - 32];
        g_q[((size_t)t * Hn + h) * Dn + d] = x * c + rot * s;
    } else {
        const int g = h - Hn;
        const float* row = g_qkvw + (size_t)t * OUTDn + KOFF + g * Dn;
        float x = row[d];
        float rot = (d < 32) ? -row[d + 32] : row[d - 32];
        g_k[((size_t)t * HKVn + g) * Dn + d] = x * c + rot * s;
    }
}

// ---------------- mean-pool ----------------
__global__ void pool_kernel() {
    int idx = blockIdx.x * blockDim.x + threadIdx.x;
    if (idx >= NBn * Gn * Dn) return;
    const int d = idx & 63;
    int rest = idx >> 6;
    const int g = rest % Gn;
    const int n = rest / Gn;
    float sk = 0.f, sv = 0.f;
    #pragma unroll 4
    for (int b = 0; b < BLKn; b++) {
        const int t = n * BLKn + b;
        sk += g_k[((size_t)t * HKVn + g) * Dn + d];
        sv += g_qkvw[(size_t)t * OUTDn + VOFF + g * Dn + d];
    }
    g_kcmp[idx] = sk * (1.f / BLKn);
    g_vcmp[idx] = sv * (1.f / BLKn);
}

// ---------------- compressed attention: CTA per (t,g), warp per head ----------------
__global__ __launch_bounds__(512) void cmp2_kernel() {
    const int t = blockIdx.x, g = blockIdx.y;
    const int tid = threadIdx.x, w = tid >> 5, lane = tid & 31;
    __shared__ float kc[NBn][65], vc[NBn][65], qs[HGn][Dn], ps[HGn][NBn];

    for (int i = tid; i < NBn * Dn; i += 512) {
        int n = i >> 6, d = i & 63;
        kc[n][d] = g_kcmp[((size_t)n * Gn + g) * Dn + d];
        vc[n][d] = g_vcmp[((size_t)n * Gn + g) * Dn + d];
    }
    for (int i = tid; i < HGn * Dn; i += 512) {
        int hg = i >> 6, d = i & 63;
        qs[hg][d] = g_q[((size_t)t * Hn + g * HGn + hg) * Dn + d];
    }
    __syncthreads();

    const int nvis = (t + 1) >> 5;
    float sc[2];
    #pragma unroll
    for (int ii = 0; ii < 2; ii++) {
        const int n = lane + ii * 32;
        float s = NEGf;
        if (n < nvis) {
            float acc = 0.f;
            #pragma unroll
            for (int d = 0; d < Dn; d++) acc = fmaf(qs[w][d], kc[n][d], acc);
            s = acc * SCALEf;
        }
        sc[ii] = s;
    }
    float p0 = 0.f, p1 = 0.f;
    if (nvis > 0) {
        float m = warpMax(fmaxf(sc[0], sc[1]));
        float e0 = expf(sc[0] - m), e1 = expf(sc[1] - m);
        float inv = 1.f / warpSum(e0 + e1);
        p0 = e0 * inv; p1 = e1 * inv;
    }
    ps[w][lane] = p0; ps[w][lane + 32] = p1;
    float* pout = g_pcmp + ((size_t)t * Hn + g * HGn + w) * NBn;
    pout[lane] = p0; pout[lane + 32] = p1;
    __syncwarp();

    float a0 = 0.f, a1 = 0.f;
    for (int n = 0; n < nvis; n++) {
        const float p = ps[w][n];
        a0 = fmaf(p, vc[n][lane], a0);
        a1 = fmaf(p, vc[n][lane + 32], a1);
    }
    float* orow = g_ocmp + ((size_t)t * Hn + g * HGn + w) * Dn;
    orow[lane] = a0; orow[lane + 32] = a1;
}

// ---------------- top-8 ----------------
__global__ void topk_kernel() {
    int idx = blockIdx.x * blockDim.x + threadIdx.x;
    if (idx >= Tn * Gn) return;
    const int g = idx % Gn, t = idx / Gn, tb = t >> 5;
    float imp[NBn];
    for (int n = 0; n < NBn; n++) {
        if (n > tb) { imp[n] = NEGf; continue; }
        float s = 0.f;
        #pragma unroll
        for (int hg = 0; hg < HGn; hg++)
            s += g_pcmp[((size_t)t * Hn + g * HGn + hg) * NBn + n];
        if (n == 0)  s += 1e4f;
        if (n == tb) s += 1e4f;
        imp[n] = s;
    }
    int* sel = g_selidx + ((size_t)t * Gn + g) * NSELn;
    for (int i = 0; i < NSELn; i++) {
        int best = 0; float bv = imp[0];
        for (int n = 1; n < NBn; n++)
            if (imp[n] > bv) { bv = imp[n]; best = n; }
        sel[i] = best;
        imp[best] = -2e30f;
    }
}

// ---------------- selection attention: CTA per (t,g) ----------------
__global__ __launch_bounds__(512) void sel2_kernel() {
    const int t = blockIdx.x, g = blockIdx.y;
    const int tid = threadIdx.x, w = tid >> 5, lane = tid & 31;
    __shared__ float kb[BLKn][65], qs[HGn][Dn], ps[HGn][NSELn * BLKn];
    __shared__ int sel[NSELn];

    for (int i = tid; i < HGn * Dn; i += 512) {
        int hg = i >> 6, d = i & 63;
        qs[hg][d] = g_q[((size_t)t * Hn + g * HGn + hg) * Dn + d];
    }
    if (tid < NSELn) sel[tid] = g_selidx[((size_t)t * Gn + g) * NSELn + tid];
    __syncthreads();

    float sc[NSELn];
    for (int i = 0; i < NSELn; i++) {
        const int base = sel[i] * BLKn;
        for (int j = tid; j < BLKn * Dn; j += 512) {
            int b = j >> 6, d = j & 63;
            kb[b][d] = g_k[((size_t)(base + b) * HKVn + g) * Dn + d];
        }
        __syncthreads();
        const int pos = base + lane;
        float s = NEGf;
        if (pos <= t) {
            float acc = 0.f;
            #pragma unroll
            for (int d = 0; d < Dn; d++) acc = fmaf(qs[w][d], kb[lane][d], acc);
            s = acc * SCALEf;
        }
        sc[i] = s;
        __syncthreads();
    }
    float lm = sc[0];
    #pragma unroll
    for (int i = 1; i < NSELn; i++) lm = fmaxf(lm, sc[i]);
    float m = warpMax(lm);
    float lsum = 0.f, ev[NSELn];
    #pragma unroll
    for (int i = 0; i < NSELn; i++) { ev[i] = expf(sc[i] - m); lsum += ev[i]; }
    float inv = 1.f / warpSum(lsum);
    #pragma unroll
    for (int i = 0; i < NSELn; i++) ps[w][i * 32 + lane] = ev[i] * inv;
    __syncwarp();

    float a0 = 0.f, a1 = 0.f;
    for (int i = 0; i < NSELn; i++) {
        const int base = sel[i] * BLKn;
        for (int j = tid; j < BLKn * Dn; j += 512) {
            int b = j >> 6, d = j & 63;
            kb[b][d] = g_qkvw[(size_t)(base + b) * OUTDn + VOFF + g * Dn + d];
        }
        __syncthreads();
        if (base <= t) {
            for (int b = 0; b < BLKn; b++) {
                const float p = ps[w][i * 32 + b];
                a0 = fmaf(p, kb[b][lane], a0);
                a1 = fmaf(p, kb[b][lane + 32], a1);
            }
        }
        __syncthreads();
    }
    float* orow = g_osel + ((size_t)t * Hn + g * HGn + w) * Dn;
    orow[lane] = a0; orow[lane + 32] = a1;
}

// ---------------- sliding window: CTA per (t,g) ----------------
__global__ __launch_bounds__(512) void win2_kernel() {
    const int t = blockIdx.x, g = blockIdx.y;
    const int tid = threadIdx.x, w = tid >> 5, lane = tid & 31;
    __shared__ float kb[BLKn][65], qs[HGn][Dn], ps[HGn][WINn];

    for (int i = tid; i < HGn * Dn; i += 512) {
        int hg = i >> 6, d = i & 63;
        qs[hg][d] = g_q[((size_t)t * Hn + g * HGn + hg) * Dn + d];
    }
    __syncthreads();

    const int p0 = t - (WINn - 1);
    float sc[8];
    for (int i = 0; i < 8; i++) {
        const int base = p0 + i * 32;
        for (int j = tid; j < BLKn * Dn; j += 512) {
            int b = j >> 6, d = j & 63;
            int row = base + b; if (row < 0) row = 0;
            kb[b][d] = g_k[((size_t)row * HKVn + g) * Dn + d];
        }
        __syncthreads();
        const int pos = base + lane;
        float s = NEGf;
        if (pos >= 0) {
            float acc = 0.f;
            #pragma unroll
            for (int d = 0; d < Dn; d++) acc = fmaf(qs[w][d], kb[lane][d], acc);
            s = acc * SCALEf;
        }
        sc[i] = s;
        __syncthreads();
    }
    float lm = sc[0];
    #pragma unroll
    for (int i = 1; i < 8; i++) lm = fmaxf(lm, sc[i]);
    float m = warpMax(lm);
    float lsum = 0.f, ev[8];
    #pragma unroll
    for (int i = 0; i < 8; i++) { ev[i] = expf(sc[i] - m); lsum += ev[i]; }
    float inv = 1.f / warpSum(lsum);
    #pragma unroll
    for (int i = 0; i < 8; i++) ps[w][i * 32 + lane] = ev[i] * inv;
    __syncwarp();

    float a0 = 0.f, a1 = 0.f;
    for (int i = 0; i < 8; i++) {
        const int base = p0 + i * 32;
        for (int j = tid; j < BLKn * Dn; j += 512) {
            int b = j >> 6, d = j & 63;
            int row = base + b; if (row < 0) row = 0;
            kb[b][d] = g_qkvw[(size_t)row * OUTDn + VOFF + g * Dn + d];
        }
        __syncthreads();
        for (int b = 0; b < BLKn; b++) {
            const float p = ps[w][i * 32 + b];
            a0 = fmaf(p, kb[b][lane], a0);
            a1 = fmaf(p, kb[b][lane + 32], a1);
        }
        __syncthreads();
    }
    float* orow = g_owin + ((size_t)t * Hn + g * HGn + w) * Dn;
    orow[lane] = a0; orow[lane + 32] = a1;
}

// ---------------- gated combine -> split-bf16 interleaved ----------------
__global__ void combine_kernel() {
    int idx = blockIdx.x * blockDim.x + threadIdx.x;
    if (idx >= Tn * Hn * Dn) return;
    const int d = idx & 63;
    int rest = idx >> 6;
    const int h = rest % Hn;
    const int t = rest / Hn;
    const float* wrow = g_qkvw + (size_t)t * OUTDn + WOFF + h * 3;
    const float g0 = 1.f / (1.f + expf(-wrow[0]));
    const float g1 = 1.f / (1.f + expf(-wrow[1]));
    const float g2 = 1.f / (1.f + expf(-wrow[2]));
    float val = g0 * g_ocmp[idx] + g1 * g_osel[idx] + g2 * g_owin[idx];
    unsigned short hh, ll;
    f32_hl(val, hh, ll);
    uint2 pk;
    pk.x = (uint32_t)hh | ((uint32_t)hh << 16);
    pk.y = (uint32_t)ll | ((uint32_t)ll << 16);
    *(uint2*)((char*)g_a2o + (size_t)idx * 8) = pk;
}

// ---------------- launch (pure kernel launches, no runtime API) ----------------
extern "C" void kernel_launch(void* const* d_in, const int* in_sizes, int n_in,
                              void* d_out, int out_size) {
    const float* x    = (const float*)d_in[0];
    const float* cosp = (const float*)d_in[1];
    const float* sinp = (const float*)d_in[2];
    const float* Wqkv = (const float*)d_in[3];
    const float* Wo   = (const float*)d_in[4];
    float* out = (float*)d_out;

    conv_x_kernel<<<(Tn * HIDn + 255) / 256, 256>>>(x);
    {
        dim3 b(32, 32);
        tr_q_kernel<<<dim3(76, 64), b>>>(Wqkv);
        tr_o_kernel<<<dim3(64, 64), b>>>(Wo);
    }
    gemm_mma_qkvw<<<dim3(NPADn / 128, Tn / 128), 256>>>();
    rope_kernel<<<(Tn * (Hn + HKVn) * Dn + 255) / 256, 256>>>(cosp, sinp);
    pool_kernel<<<(NBn * Gn * Dn + 255) / 256, 256>>>();
    cmp2_kernel<<<dim3(Tn, Gn), 512>>>();
    topk_kernel<<<(Tn * Gn + 255) / 256, 256>>>();
    sel2_kernel<<<dim3(Tn, Gn), 512>>>();
    win2_kernel<<<dim3(Tn, Gn), 512>>>();
    combine_kernel<<<(Tn * Hn * Dn + 255) / 256, 256>>>();
    gemm_mma_out<<<dim3(HIDn / 128, Tn / 128), 256>>>(out);
}

// round 8
// speedup vs baseline: 2.2341x; 1.0562x over previous
#include <cuda_runtime.h>
#include <cuda_bf16.h>
#include <cstdint>
#include <math.h>

#define Tn    2048
#define HIDn  2048
#define Hn    32
#define HKVn  2
#define Dn    64
#define Gn    2
#define HGn   16
#define BLKn  32
#define NSELn 8
#define WINn  256
#define NBn   64
#define OUTDn 2400
#define NPADn 2432          /* 19*128 */
#define K2n   6144          /* 3x K=2048 : [ah,ah,al] x [bh,bl,bh] */
#define KOFF  (Hn*Dn)
#define VOFF  (KOFF + HKVn*Dn)
#define WOFF  (VOFF + HKVn*Dn)
#define NEGf  (-1e30f)
#define SCALEf 0.125f

// ---------------- scratch ----------------
__device__ float g_qkvw[Tn*OUTDn];
__device__ float g_q[Tn*Hn*Dn];
__device__ float g_k[Tn*HKVn*Dn];
__device__ float g_kcmp[NBn*Gn*Dn];
__device__ float g_vcmp[NBn*Gn*Dn];
__device__ float g_pcmp[Tn*Hn*NBn];
__device__ float g_ocmp[Tn*Hn*Dn];
__device__ float g_osel[Tn*Hn*Dn];
__device__ float g_owin[Tn*Hn*Dn];
__device__ int   g_selidx[Tn*Gn*NSELn];
__device__ __align__(16) __nv_bfloat16 g_a2x[(size_t)Tn*K2n];
__device__ __align__(16) __nv_bfloat16 g_a2o[(size_t)Tn*K2n];
__device__ __align__(16) __nv_bfloat16 g_b2q[(size_t)NPADn*K2n];
__device__ __align__(16) __nv_bfloat16 g_b2o[(size_t)HIDn*K2n];

// ---------------- helpers ----------------
__device__ __forceinline__ uint32_t smem_u32(const void* p) {
    uint32_t a;
    asm("{ .reg .u64 t; cvta.to.shared.u64 t, %1; cvt.u32.u64 %0, t; }" : "=r"(a) : "l"(p));
    return a;
}
#define CP_ASYNC16(dst, src) \
    asm volatile("cp.async.cg.shared.global [%0], [%1], 16;" :: "r"(dst), "l"(src) : "memory")
#define CP_COMMIT() asm volatile("cp.async.commit_group;" ::: "memory")
#define CP_WAIT2()  asm volatile("cp.async.wait_group 2;" ::: "memory")
#define CP_WAIT0()  asm volatile("cp.async.wait_group 0;" ::: "memory")

__device__ __forceinline__ void ldsm4(uint32_t &r0, uint32_t &r1, uint32_t &r2, uint32_t &r3,
                                      uint32_t addr) {
    asm volatile("ldmatrix.sync.aligned.m8n8.x4.shared.b16 {%0,%1,%2,%3}, [%4];"
                 : "=r"(r0), "=r"(r1), "=r"(r2), "=r"(r3) : "r"(addr));
}
__device__ __forceinline__ void mma_bf16(float* c, uint32_t a0, uint32_t a1, uint32_t a2,
                                         uint32_t a3, uint32_t b0, uint32_t b1) {
    asm volatile("mma.sync.aligned.m16n8k16.row.col.f32.bf16.bf16.f32 "
                 "{%0,%1,%2,%3}, {%4,%5,%6,%7}, {%8,%9}, {%0,%1,%2,%3};"
                 : "+f"(c[0]), "+f"(c[1]), "+f"(c[2]), "+f"(c[3])
                 : "r"(a0), "r"(a1), "r"(a2), "r"(a3), "r"(b0), "r"(b1));
}

__device__ __forceinline__ float warpMax(float v) {
    #pragma unroll
    for (int o = 16; o > 0; o >>= 1) v = fmaxf(v, __shfl_xor_sync(0xffffffffu, v, o));
    return v;
}
__device__ __forceinline__ float warpSum(float v) {
    #pragma unroll
    for (int o = 16; o > 0; o >>= 1) v += __shfl_xor_sync(0xffffffffu, v, o);
    return v;
}
__device__ __forceinline__ void f32_hl(float v, unsigned short &h, unsigned short &l) {
    __nv_bfloat16 bh = __float2bfloat16(v);
    float r = v - __bfloat162float(bh);
    __nv_bfloat16 bl = __float2bfloat16(r);
    h = __bfloat16_as_ushort(bh);
    l = __bfloat16_as_ushort(bl);
}

// ---------------- mma.sync split-bf16 GEMM body ----------------
// C[M,N] = A2[M,K2] @ B2[N,K2]^T ; 128x128 CTA tile, K-chunk 16, 4-stage cp.async.
#define SAst 24                          /* smem row stride in bf16 elems (48 B) */
#define STAGE_BYTES (128*SAst*2)         /* 6144 per operand */
#define STAGE_PAIR  (2*STAGE_BYTES)      /* 12288 */
__device__ __forceinline__ void gemm_body(const __nv_bfloat16* __restrict__ A2,
                                          const __nv_bfloat16* __restrict__ B2,
                                          float* __restrict__ C,
                                          int Nvalid, int ldc) {
    __shared__ __align__(16) unsigned char smem[4 * STAGE_PAIR];   // 48 KB
    const uint32_t sbase = smem_u32(smem);
    const int tid = threadIdx.x;
    const int lane = tid & 31;
    const int warp = tid >> 5;
    const int wm = warp >> 2;
    const int wn = warp & 3;
    const int m0 = blockIdx.y * 128;
    const int n0 = blockIdx.x * 128;

    // global loads: 2 threads per row, 8 bf16 (16B) each
    const int lrow = tid >> 1;
    const int lk   = (tid & 1) * 8;
    const __nv_bfloat16* aG = A2 + (size_t)(m0 + lrow) * K2n + lk;
    const __nv_bfloat16* bG = B2 + (size_t)(n0 + lrow) * K2n + lk;
    const uint32_t wOff = (uint32_t)(lrow * SAst + lk) * 2;

    float acc[4][4][4];
    #pragma unroll
    for (int i = 0; i < 4; i++)
        #pragma unroll
        for (int j = 0; j < 4; j++)
            #pragma unroll
            for (int r = 0; r < 4; r++) acc[i][j][r] = 0.f;

    const int NK = K2n / 16;   // 384

    const uint32_t aRow = (uint32_t)(wm * 64 + (lane & 15));
    const uint32_t aColSel = (uint32_t)((lane >> 4) * 8);
    const int ro = lane >> 3;
    const uint32_t bRow = (uint32_t)(wn * 32 + ((ro & 2) ? 8 : 0) + (lane & 7));
    const uint32_t bColSel = (uint32_t)((ro & 1) ? 8 : 0);

    // prologue: stages 0..2
    #pragma unroll
    for (int s = 0; s < 3; s++) {
        uint32_t sA = sbase + (uint32_t)s * STAGE_PAIR;
        uint32_t sB = sA + STAGE_BYTES;
        CP_ASYNC16(sA + wOff, aG + (size_t)s * 16);
        CP_ASYNC16(sB + wOff, bG + (size_t)s * 16);
        CP_COMMIT();
    }

    for (int kc = 0; kc < NK; kc++) {
        if (kc + 3 < NK) CP_WAIT2(); else CP_WAIT0();
        __syncthreads();

        // prefetch stage kc+3 (ring slot (kc+3)&3 == (kc-1)&3, fully consumed)
        if (kc + 3 < NK) {
            uint32_t st = (uint32_t)((kc + 3) & 3) * STAGE_PAIR;
            uint32_t sA = sbase + st;
            uint32_t sB = sA + STAGE_BYTES;
            CP_ASYNC16(sA + wOff, aG + (size_t)(kc + 3) * 16);
            CP_ASYNC16(sB + wOff, bG + (size_t)(kc + 3) * 16);
            CP_COMMIT();
        }

        uint32_t st = (uint32_t)(kc & 3) * STAGE_PAIR;
        uint32_t sA = sbase + st;
        uint32_t sB = sA + STAGE_BYTES;

        uint32_t af[4][4];
        #pragma unroll
        for (int i = 0; i < 4; i++) {
            uint32_t addr = sA + ((aRow + i * 16) * SAst + aColSel) * 2;
            ldsm4(af[i][0], af[i][1], af[i][2], af[i][3], addr);
        }
        uint32_t bf[4][2];
        #pragma unroll
        for (int j2 = 0; j2 < 2; j2++) {
            uint32_t addr = sB + ((bRow + j2 * 16) * SAst + bColSel) * 2;
            uint32_t r0, r1, r2, r3;
            ldsm4(r0, r1, r2, r3, addr);
            bf[2*j2][0] = r0; bf[2*j2][1] = r1;
            bf[2*j2+1][0] = r2; bf[2*j2+1][1] = r3;
        }
        #pragma unroll
        for (int i = 0; i < 4; i++)
            #pragma unroll
            for (int j = 0; j < 4; j++)
                mma_bf16(acc[i][j], af[i][0], af[i][1], af[i][2], af[i][3],
                         bf[j][0], bf[j][1]);
    }

    const int rbase = m0 + wm * 64 + (lane >> 2);
    const int cbase = n0 + wn * 32 + (lane & 3) * 2;
    #pragma unroll
    for (int i = 0; i < 4; i++) {
        #pragma unroll
        for (int j = 0; j < 4; j++) {
            int rr = rbase + i * 16;
            int cc = cbase + j * 8;
            if (cc < Nvalid) {
                float* p0 = C + (size_t)rr * ldc + cc;
                p0[0] = acc[i][j][0];
                if (cc + 1 < Nvalid) p0[1] = acc[i][j][1];
                float* p1 = C + (size_t)(rr + 8) * ldc + cc;
                p1[0] = acc[i][j][2];
                if (cc + 1 < Nvalid) p1[1] = acc[i][j][3];
            }
        }
    }
}

__global__ __launch_bounds__(256) void gemm_mma_qkvw() {
    gemm_body(g_a2x, g_b2q, g_qkvw, OUTDn, OUTDn);
}
__global__ __launch_bounds__(256) void gemm_mma_out(float* __restrict__ C) {
    gemm_body(g_a2o, g_b2o, C, HIDn, HIDn);
}

// ---------------- conversions (3-term split: A=[h,h,l], B=[h,l,h]) ----------------
__global__ void conv_x_kernel(const float* __restrict__ x) {
    int idx = blockIdx.x * blockDim.x + threadIdx.x;
    if (idx >= Tn * HIDn) return;
    unsigned short h, l;
    f32_hl(x[idx], h, l);
    unsigned short* p = (unsigned short*)g_a2x + (size_t)idx * 3;
    p[0] = h; p[1] = h; p[2] = l;
}
__device__ __forceinline__ void tr_body(const float* __restrict__ W,
                                        __nv_bfloat16* __restrict__ B2,
                                        int Ncols, int Npad) {
    __shared__ float tile[32][33];
    int n = blockIdx.x * 32 + threadIdx.x;
    int k = blockIdx.y * 32 + threadIdx.y;
    tile[threadIdx.y][threadIdx.x] = (n < Ncols) ? W[(size_t)k * Ncols + n] : 0.f;
    __syncthreads();
    int nn = blockIdx.x * 32 + threadIdx.y;
    int kk = blockIdx.y * 32 + threadIdx.x;
    if (nn < Npad) {
        unsigned short h, l;
        f32_hl(tile[threadIdx.x][threadIdx.y], h, l);
        unsigned short* p = (unsigned short*)B2 + (size_t)nn * K2n + (size_t)kk * 3;
        p[0] = h; p[1] = l; p[2] = h;
    }
}
__global__ void tr_q_kernel(const float* __restrict__ W) { tr_body(W, g_b2q, OUTDn, NPADn); }
__global__ void tr_o_kernel(const float* __restrict__ W) { tr_body(W, g_b2o, HIDn, HIDn); }

// ---------------- RoPE ----------------
__global__ void rope_kernel(const float* __restrict__ cosp, const float* __restrict__ sinp) {
    int idx = blockIdx.x * blockDim.x + threadIdx.x;
    const int total = Tn * (Hn + HKVn) * Dn;
    if (idx >= total) return;
    const int d = idx & 63;
    int rest = idx >> 6;
    const int h = rest % (Hn + HKVn);
    const int t = rest / (Hn + HKVn);
    const float c = cosp[t * Dn + d];
    const float s = sinp[t * Dn + d];
    if (h < Hn) {
        const float* row = g_qkvw + (size_t)t * OUTDn + h * Dn;
        float x = row[d];
        float rot = (d < 32) ? -row[d + 32] : row[d - 32];
        g_q[((size_t)t * Hn + h) * Dn + d] = x * c + rot * s;
    } else {
        const int g = h - Hn;
        const float* row = g_qkvw + (size_t)t * OUTDn + KOFF + g * Dn;
        float x = row[d];
        float rot = (d < 32) ? -row[d + 32] : row[d - 32];
        g_k[((size_t)t * HKVn + g) * Dn + d] = x * c + rot * s;
    }
}

// ---------------- mean-pool ----------------
__global__ void pool_kernel() {
    int idx = blockIdx.x * blockDim.x + threadIdx.x;
    if (idx >= NBn * Gn * Dn) return;
    const int d = idx & 63;
    int rest = idx >> 6;
    const int g = rest % Gn;
    const int n = rest / Gn;
    float sk = 0.f, sv = 0.f;
    #pragma unroll 4
    for (int b = 0; b < BLKn; b++) {
        const int t = n * BLKn + b;
        sk += g_k[((size_t)t * HKVn + g) * Dn + d];
        sv += g_qkvw[(size_t)t * OUTDn + VOFF + g * Dn + d];
    }
    g_kcmp[idx] = sk * (1.f / BLKn);
    g_vcmp[idx] = sv * (1.f / BLKn);
}

// ---------------- compressed attention: CTA per (t,g), warp per head ----------------
__global__ __launch_bounds__(512) void cmp2_kernel() {
    const int t = blockIdx.x, g = blockIdx.y;
    const int tid = threadIdx.x, w = tid >> 5, lane = tid & 31;
    __shared__ float kc[NBn][65], vc[NBn][65], qs[HGn][Dn], ps[HGn][NBn];

    for (int i = tid; i < NBn * Dn; i += 512) {
        int n = i >> 6, d = i & 63;
        kc[n][d] = g_kcmp[((size_t)n * Gn + g) * Dn + d];
        vc[n][d] = g_vcmp[((size_t)n * Gn + g) * Dn + d];
    }
    for (int i = tid; i < HGn * Dn; i += 512) {
        int hg = i >> 6, d = i & 63;
        qs[hg][d] = g_q[((size_t)t * Hn + g * HGn + hg) * Dn + d];
    }
    __syncthreads();

    const int nvis = (t + 1) >> 5;
    float sc[2];
    #pragma unroll
    for (int ii = 0; ii < 2; ii++) {
        const int n = lane + ii * 32;
        float s = NEGf;
        if (n < nvis) {
            float acc = 0.f;
            #pragma unroll
            for (int d = 0; d < Dn; d++) acc = fmaf(qs[w][d], kc[n][d], acc);
            s = acc * SCALEf;
        }
        sc[ii] = s;
    }
    float p0 = 0.f, p1 = 0.f;
    if (nvis > 0) {
        float m = warpMax(fmaxf(sc[0], sc[1]));
        float e0 = expf(sc[0] - m), e1 = expf(sc[1] - m);
        float inv = 1.f / warpSum(e0 + e1);
        p0 = e0 * inv; p1 = e1 * inv;
    }
    ps[w][lane] = p0; ps[w][lane + 32] = p1;
    float* pout = g_pcmp + ((size_t)t * Hn + g * HGn + w) * NBn;
    pout[lane] = p0; pout[lane + 32] = p1;
    __syncwarp();

    float a0 = 0.f, a1 = 0.f;
    for (int n = 0; n < nvis; n++) {
        const float p = ps[w][n];
        a0 = fmaf(p, vc[n][lane], a0);
        a1 = fmaf(p, vc[n][lane + 32], a1);
    }
    float* orow = g_ocmp + ((size_t)t * Hn + g * HGn + w) * Dn;
    orow[lane] = a0; orow[lane + 32] = a1;
}

// ---------------- top-8 ----------------
__global__ void topk_kernel() {
    int idx = blockIdx.x * blockDim.x + threadIdx.x;
    if (idx >= Tn * Gn) return;
    const int g = idx % Gn, t = idx / Gn, tb = t >> 5;
    float imp[NBn];
    for (int n = 0; n < NBn; n++) {
        if (n > tb) { imp[n] = NEGf; continue; }
        float s = 0.f;
        #pragma unroll
        for (int hg = 0; hg < HGn; hg++)
            s += g_pcmp[((size_t)t * Hn + g * HGn + hg) * NBn + n];
        if (n == 0)  s += 1e4f;
        if (n == tb) s += 1e4f;
        imp[n] = s;
    }
    int* sel = g_selidx + ((size_t)t * Gn + g) * NSELn;
    for (int i = 0; i < NSELn; i++) {
        int best = 0; float bv = imp[0];
        for (int n = 1; n < NBn; n++)
            if (imp[n] > bv) { bv = imp[n]; best = n; }
        sel[i] = best;
        imp[best] = -2e30f;
    }
}

// ---------------- selection attention: CTA per (t,g) ----------------
__global__ __launch_bounds__(512) void sel2_kernel() {
    const int t = blockIdx.x, g = blockIdx.y;
    const int tid = threadIdx.x, w = tid >> 5, lane = tid & 31;
    __shared__ float kb[BLKn][65], qs[HGn][Dn], ps[HGn][NSELn * BLKn];
    __shared__ int sel[NSELn];

    for (int i = tid; i < HGn * Dn; i += 512) {
        int hg = i >> 6, d = i & 63;
        qs[hg][d] = g_q[((size_t)t * Hn + g * HGn + hg) * Dn + d];
    }
    if (tid < NSELn) sel[tid] = g_selidx[((size_t)t * Gn + g) * NSELn + tid];
    __syncthreads();

    float sc[NSELn];
    for (int i = 0; i < NSELn; i++) {
        const int base = sel[i] * BLKn;
        for (int j = tid; j < BLKn * Dn; j += 512) {
            int b = j >> 6, d = j & 63;
            kb[b][d] = g_k[((size_t)(base + b) * HKVn + g) * Dn + d];
        }
        __syncthreads();
        const int pos = base + lane;
        float s = NEGf;
        if (pos <= t) {
            float acc = 0.f;
            #pragma unroll
            for (int d = 0; d < Dn; d++) acc = fmaf(qs[w][d], kb[lane][d], acc);
            s = acc * SCALEf;
        }
        sc[i] = s;
        __syncthreads();
    }
    float lm = sc[0];
    #pragma unroll
    for (int i = 1; i < NSELn; i++) lm = fmaxf(lm, sc[i]);
    float m = warpMax(lm);
    float lsum = 0.f, ev[NSELn];
    #pragma unroll
    for (int i = 0; i < NSELn; i++) { ev[i] = expf(sc[i] - m); lsum += ev[i]; }
    float inv = 1.f / warpSum(lsum);
    #pragma unroll
    for (int i = 0; i < NSELn; i++) ps[w][i * 32 + lane] = ev[i] * inv;
    __syncwarp();

    float a0 = 0.f, a1 = 0.f;
    for (int i = 0; i < NSELn; i++) {
        const int base = sel[i] * BLKn;
        for (int j = tid; j < BLKn * Dn; j += 512) {
            int b = j >> 6, d = j & 63;
            kb[b][d] = g_qkvw[(size_t)(base + b) * OUTDn + VOFF + g * Dn + d];
        }
        __syncthreads();
        if (base <= t) {
            for (int b = 0; b < BLKn; b++) {
                const float p = ps[w][i * 32 + b];
                a0 = fmaf(p, kb[b][lane], a0);
                a1 = fmaf(p, kb[b][lane + 32], a1);
            }
        }
        __syncthreads();
    }
    float* orow = g_osel + ((size_t)t * Hn + g * HGn + w) * Dn;
    orow[lane] = a0; orow[lane + 32] = a1;
}

// ---------------- sliding window: CTA per (t,g) ----------------
__global__ __launch_bounds__(512) void win2_kernel() {
    const int t = blockIdx.x, g = blockIdx.y;
    const int tid = threadIdx.x, w = tid >> 5, lane = tid & 31;
    __shared__ float kb[BLKn][65], qs[HGn][Dn], ps[HGn][WINn];

    for (int i = tid; i < HGn * Dn; i += 512) {
        int hg = i >> 6, d = i & 63;
        qs[hg][d] = g_q[((size_t)t * Hn + g * HGn + hg) * Dn + d];
    }
    __syncthreads();

    const int p0 = t - (WINn - 1);
    float sc[8];
    for (int i = 0; i < 8; i++) {
        const int base = p0 + i * 32;
        for (int j = tid; j < BLKn * Dn; j += 512) {
            int b = j >> 6, d = j & 63;
            int row = base + b; if (row < 0) row = 0;
            kb[b][d] = g_k[((size_t)row * HKVn + g) * Dn + d];
        }
        __syncthreads();
        const int pos = base + lane;
        float s = NEGf;
        if (pos >= 0) {
            float acc = 0.f;
            #pragma unroll
            for (int d = 0; d < Dn; d++) acc = fmaf(qs[w][d], kb[lane][d], acc);
            s = acc * SCALEf;
        }
        sc[i] = s;
        __syncthreads();
    }
    float lm = sc[0];
    #pragma unroll
    for (int i = 1; i < 8; i++) lm = fmaxf(lm, sc[i]);
    float m = warpMax(lm);
    float lsum = 0.f, ev[8];
    #pragma unroll
    for (int i = 0; i < 8; i++) { ev[i] = expf(sc[i] - m); lsum += ev[i]; }
    float inv = 1.f / warpSum(lsum);
    #pragma unroll
    for (int i = 0; i < 8; i++) ps[w][i * 32 + lane] = ev[i] * inv;
    __syncwarp();

    float a0 = 0.f, a1 = 0.f;
    for (int i = 0; i < 8; i++) {
        const int base = p0 + i * 32;
        for (int j = tid; j < BLKn * Dn; j += 512) {
            int b = j >> 6, d = j & 63;
            int row = base + b; if (row < 0) row = 0;
            kb[b][d] = g_qkvw[(size_t)row * OUTDn + VOFF + g * Dn + d];
        }
        __syncthreads();
        for (int b = 0; b < BLKn; b++) {
            const float p = ps[w][i * 32 + b];
            a0 = fmaf(p, kb[b][lane], a0);
            a1 = fmaf(p, kb[b][lane + 32], a1);
        }
        __syncthreads();
    }
    float* orow = g_owin + ((size_t)t * Hn + g * HGn + w) * Dn;
    orow[lane] = a0; orow[lane + 32] = a1;
}

// ---------------- gated combine -> 3-term split A operand ----------------
__global__ void combine_kernel() {
    int idx = blockIdx.x * blockDim.x + threadIdx.x;
    if (idx >= Tn * Hn * Dn) return;
    const int d = idx & 63;
    int rest = idx >> 6;
    const int h = rest % Hn;
    const int t = rest / Hn;
    const float* wrow = g_qkvw + (size_t)t * OUTDn + WOFF + h * 3;
    const float g0 = 1.f / (1.f + expf(-wrow[0]));
    const float g1 = 1.f / (1.f + expf(-wrow[1]));
    const float g2 = 1.f / (1.f + expf(-wrow[2]));
    float val = g0 * g_ocmp[idx] + g1 * g_osel[idx] + g2 * g_owin[idx];
    unsigned short hh, ll;
    f32_hl(val, hh, ll);
    unsigned short* p = (unsigned short*)g_a2o + (size_t)idx * 3;
    p[0] = hh; p[1] = hh; p[2] = ll;
}

// ---------------- launch (pure kernel launches) ----------------
extern "C" void kernel_launch(void* const* d_in, const int* in_sizes, int n_in,
                              void* d_out, int out_size) {
    const float* x    = (const float*)d_in[0];
    const float* cosp = (const float*)d_in[1];
    const float* sinp = (const float*)d_in[2];
    const float* Wqkv = (const float*)d_in[3];
    const float* Wo   = (const float*)d_in[4];
    float* out = (float*)d_out;

    conv_x_kernel<<<(Tn * HIDn + 255) / 256, 256>>>(x);
    {
        dim3 b(32, 32);
        tr_q_kernel<<<dim3(76, 64), b>>>(Wqkv);
        tr_o_kernel<<<dim3(64, 64), b>>>(Wo);
    }
    gemm_mma_qkvw<<<dim3(NPADn / 128, Tn / 128), 256>>>();
    rope_kernel<<<(Tn * (Hn + HKVn) * Dn + 255) / 256, 256>>>(cosp, sinp);
    pool_kernel<<<(NBn * Gn * Dn + 255) / 256, 256>>>();
    cmp2_kernel<<<dim3(Tn, Gn), 512>>>();
    topk_kernel<<<(Tn * Gn + 255) / 256, 256>>>();
    sel2_kernel<<<dim3(Tn, Gn), 512>>>();
    win2_kernel<<<dim3(Tn, Gn), 512>>>();
    combine_kernel<<<(Tn * Hn * Dn + 255) / 256, 256>>>();
    gemm_mma_out<<<dim3(HIDn / 128, Tn / 128), 256>>>(out);
}

// round 9
// speedup vs baseline: 2.3463x; 1.0502x over previous
#include <cuda_runtime.h>
#include <cuda_bf16.h>
#include <cstdint>
#include <math.h>

#define Tn    2048
#define HIDn  2048
#define Hn    32
#define HKVn  2
#define Dn    64
#define Gn    2
#define HGn   16
#define BLKn  32
#define NSELn 8
#define WINn  256
#define NBn   64
#define OUTDn 2400
#define NPADn 2432          /* 19*128 */
#define K2n   6144          /* 3x K=2048 : [ah,ah,al] x [bh,bl,bh] */
#define KOFF  (Hn*Dn)
#define VOFF  (KOFF + HKVn*Dn)
#define WOFF  (VOFF + HKVn*Dn)
#define NEGf  (-1e30f)
#define SCALEf 0.125f

// ---------------- scratch ----------------
__device__ float g_qkvw[Tn*OUTDn];
__device__ float g_q[Tn*Hn*Dn];
__device__ float g_k[Tn*HKVn*Dn];
__device__ float g_kcmp[NBn*Gn*Dn];
__device__ float g_vcmp[NBn*Gn*Dn];
__device__ float g_pcmp[Tn*Hn*NBn];
__device__ float g_ocmp[Tn*Hn*Dn];
__device__ float g_osel[Tn*Hn*Dn];
__device__ float g_owin[Tn*Hn*Dn];
__device__ int   g_selidx[Tn*Gn*NSELn];
__device__ __align__(16) __nv_bfloat16 g_a2x[(size_t)Tn*K2n];
__device__ __align__(16) __nv_bfloat16 g_a2o[(size_t)Tn*K2n];
__device__ __align__(16) __nv_bfloat16 g_b2q[(size_t)NPADn*K2n];
__device__ __align__(16) __nv_bfloat16 g_b2o[(size_t)HIDn*K2n];

// ---------------- helpers ----------------
__device__ __forceinline__ uint32_t smem_u32(const void* p) {
    uint32_t a;
    asm("{ .reg .u64 t; cvta.to.shared.u64 t, %1; cvt.u32.u64 %0, t; }" : "=r"(a) : "l"(p));
    return a;
}
#define CP_ASYNC16(dst, src) \
    asm volatile("cp.async.cg.shared.global [%0], [%1], 16;" :: "r"(dst), "l"(src) : "memory")
#define CP_COMMIT() asm volatile("cp.async.commit_group;" ::: "memory")
#define CP_WAIT1()  asm volatile("cp.async.wait_group 1;" ::: "memory")
#define CP_WAIT0()  asm volatile("cp.async.wait_group 0;" ::: "memory")

__device__ __forceinline__ void ldsm4(uint32_t &r0, uint32_t &r1, uint32_t &r2, uint32_t &r3,
                                      uint32_t addr) {
    asm volatile("ldmatrix.sync.aligned.m8n8.x4.shared.b16 {%0,%1,%2,%3}, [%4];"
                 : "=r"(r0), "=r"(r1), "=r"(r2), "=r"(r3) : "r"(addr));
}
__device__ __forceinline__ void mma_bf16(float* c, uint32_t a0, uint32_t a1, uint32_t a2,
                                         uint32_t a3, uint32_t b0, uint32_t b1) {
    asm volatile("mma.sync.aligned.m16n8k16.row.col.f32.bf16.bf16.f32 "
                 "{%0,%1,%2,%3}, {%4,%5,%6,%7}, {%8,%9}, {%0,%1,%2,%3};"
                 : "+f"(c[0]), "+f"(c[1]), "+f"(c[2]), "+f"(c[3])
                 : "r"(a0), "r"(a1), "r"(a2), "r"(a3), "r"(b0), "r"(b1));
}

__device__ __forceinline__ float warpMax(float v) {
    #pragma unroll
    for (int o = 16; o > 0; o >>= 1) v = fmaxf(v, __shfl_xor_sync(0xffffffffu, v, o));
    return v;
}
__device__ __forceinline__ float warpSum(float v) {
    #pragma unroll
    for (int o = 16; o > 0; o >>= 1) v += __shfl_xor_sync(0xffffffffu, v, o);
    return v;
}
__device__ __forceinline__ void f32_hl(float v, unsigned short &h, unsigned short &l) {
    __nv_bfloat16 bh = __float2bfloat16(v);
    float r = v - __bfloat162float(bh);
    __nv_bfloat16 bl = __float2bfloat16(r);
    h = __bfloat16_as_ushort(bh);
    l = __bfloat16_as_ushort(bl);
}

// ---------------- mma.sync split-bf16 GEMM body ----------------
// C[M,N] = A2[M,K2] @ B2[N,K2]^T ; 128x128 CTA tile, K-chunk 32, 3-stage dynamic smem.
#define SAst 40                          /* smem row stride in bf16 elems (80 B) */
#define STAGE_BYTES (128*SAst*2)         /* 10240 per operand */
#define STAGE_PAIR  (2*STAGE_BYTES)      /* 20480 */
#define NSTAGE 3
#define GEMM_SMEM (NSTAGE*STAGE_PAIR)    /* 61440 */
__device__ __forceinline__ void gemm_body(const __nv_bfloat16* __restrict__ A2,
                                          const __nv_bfloat16* __restrict__ B2,
                                          float* __restrict__ C,
                                          int Nvalid, int ldc) {
    extern __shared__ __align__(16) unsigned char smem[];
    const uint32_t sbase = smem_u32(smem);
    const int tid = threadIdx.x;
    const int lane = tid & 31;
    const int warp = tid >> 5;
    const int wm = warp >> 2;
    const int wn = warp & 3;
    const int m0 = blockIdx.y * 128;
    const int n0 = blockIdx.x * 128;

    // global loads: 4 threads per row (8 bf16 = 16B each), rows lrow and lrow+64
    const int lrow = tid >> 2;
    const int lk   = (tid & 3) * 8;
    const __nv_bfloat16* aG = A2 + (size_t)(m0 + lrow) * K2n + lk;
    const __nv_bfloat16* bG = B2 + (size_t)(n0 + lrow) * K2n + lk;
    const uint32_t wOff0 = (uint32_t)(lrow * SAst + lk) * 2;
    const uint32_t wOff1 = (uint32_t)((lrow + 64) * SAst + lk) * 2;

    float acc[4][4][4];
    #pragma unroll
    for (int i = 0; i < 4; i++)
        #pragma unroll
        for (int j = 0; j < 4; j++)
            #pragma unroll
            for (int r = 0; r < 4; r++) acc[i][j][r] = 0.f;

    const int NK = K2n / 32;   // 192

    const uint32_t aRow = (uint32_t)(wm * 64 + (lane & 15));
    const uint32_t aColSel = (uint32_t)((lane >> 4) * 8);
    const int ro = lane >> 3;
    const uint32_t bRow = (uint32_t)(wn * 32 + ((ro & 2) ? 8 : 0) + (lane & 7));
    const uint32_t bColSel = (uint32_t)((ro & 1) ? 8 : 0);

    // prologue: stages 0..1
    #pragma unroll
    for (int s = 0; s < 2; s++) {
        uint32_t sA = sbase + (uint32_t)s * STAGE_PAIR;
        uint32_t sB = sA + STAGE_BYTES;
        CP_ASYNC16(sA + wOff0, aG + (size_t)s * 32);
        CP_ASYNC16(sA + wOff1, aG + (size_t)64 * K2n + (size_t)s * 32);
        CP_ASYNC16(sB + wOff0, bG + (size_t)s * 32);
        CP_ASYNC16(sB + wOff1, bG + (size_t)64 * K2n + (size_t)s * 32);
        CP_COMMIT();
    }

    for (int kc = 0; kc < NK; kc++) {
        if (kc + 2 < NK) CP_WAIT1(); else CP_WAIT0();
        __syncthreads();

        // prefetch stage kc+2 into ring slot (kc+2)%3 == (kc-1)%3 (consumed last iter)
        if (kc + 2 < NK) {
            uint32_t st = (uint32_t)((kc + 2) % 3) * STAGE_PAIR;
            uint32_t sA = sbase + st;
            uint32_t sB = sA + STAGE_BYTES;
            CP_ASYNC16(sA + wOff0, aG + (size_t)(kc + 2) * 32);
            CP_ASYNC16(sA + wOff1, aG + (size_t)64 * K2n + (size_t)(kc + 2) * 32);
            CP_ASYNC16(sB + wOff0, bG + (size_t)(kc + 2) * 32);
            CP_ASYNC16(sB + wOff1, bG + (size_t)64 * K2n + (size_t)(kc + 2) * 32);
            CP_COMMIT();
        }

        uint32_t st = (uint32_t)(kc % 3) * STAGE_PAIR;
        uint32_t sA = sbase + st;
        uint32_t sB = sA + STAGE_BYTES;

        #pragma unroll
        for (int s = 0; s < 2; s++) {
            uint32_t af[4][4];
            #pragma unroll
            for (int i = 0; i < 4; i++) {
                uint32_t addr = sA + ((aRow + i * 16) * SAst + s * 16 + aColSel) * 2;
                ldsm4(af[i][0], af[i][1], af[i][2], af[i][3], addr);
            }
            uint32_t bf[4][2];
            #pragma unroll
            for (int j2 = 0; j2 < 2; j2++) {
                uint32_t addr = sB + ((bRow + j2 * 16) * SAst + s * 16 + bColSel) * 2;
                uint32_t r0, r1, r2, r3;
                ldsm4(r0, r1, r2, r3, addr);
                bf[2*j2][0] = r0; bf[2*j2][1] = r1;
                bf[2*j2+1][0] = r2; bf[2*j2+1][1] = r3;
            }
            #pragma unroll
            for (int i = 0; i < 4; i++)
                #pragma unroll
                for (int j = 0; j < 4; j++)
                    mma_bf16(acc[i][j], af[i][0], af[i][1], af[i][2], af[i][3],
                             bf[j][0], bf[j][1]);
        }
    }

    const int rbase = m0 + wm * 64 + (lane >> 2);
    const int cbase = n0 + wn * 32 + (lane & 3) * 2;
    #pragma unroll
    for (int i = 0; i < 4; i++) {
        #pragma unroll
        for (int j = 0; j < 4; j++) {
            int rr = rbase + i * 16;
            int cc = cbase + j * 8;
            if (cc < Nvalid) {
                float* p0 = C + (size_t)rr * ldc + cc;
                p0[0] = acc[i][j][0];
                if (cc + 1 < Nvalid) p0[1] = acc[i][j][1];
                float* p1 = C + (size_t)(rr + 8) * ldc + cc;
                p1[0] = acc[i][j][2];
                if (cc + 1 < Nvalid) p1[1] = acc[i][j][3];
            }
        }
    }
}

__global__ __launch_bounds__(256) void gemm_mma_qkvw() {
    gemm_body(g_a2x, g_b2q, g_qkvw, OUTDn, OUTDn);
}
__global__ __launch_bounds__(256) void gemm_mma_out(float* __restrict__ C) {
    gemm_body(g_a2o, g_b2o, C, HIDn, HIDn);
}

// ---------------- conversions (3-term split: A=[h,h,l], B=[h,l,h]) ----------------
__global__ void conv_x_kernel(const float* __restrict__ x) {
    int idx = blockIdx.x * blockDim.x + threadIdx.x;
    if (idx >= Tn * HIDn) return;
    unsigned short h, l;
    f32_hl(x[idx], h, l);
    unsigned short* p = (unsigned short*)g_a2x + (size_t)idx * 3;
    p[0] = h; p[1] = h; p[2] = l;
}
__device__ __forceinline__ void tr_body(const float* __restrict__ W,
                                        __nv_bfloat16* __restrict__ B2,
                                        int Ncols, int Npad) {
    __shared__ float tile[32][33];
    int n = blockIdx.x * 32 + threadIdx.x;
    int k = blockIdx.y * 32 + threadIdx.y;
    tile[threadIdx.y][threadIdx.x] = (n < Ncols) ? W[(size_t)k * Ncols + n] : 0.f;
    __syncthreads();
    int nn = blockIdx.x * 32 + threadIdx.y;
    int kk = blockIdx.y * 32 + threadIdx.x;
    if (nn < Npad) {
        unsigned short h, l;
        f32_hl(tile[threadIdx.x][threadIdx.y], h, l);
        unsigned short* p = (unsigned short*)B2 + (size_t)nn * K2n + (size_t)kk * 3;
        p[0] = h; p[1] = l; p[2] = h;
    }
}
__global__ void tr_q_kernel(const float* __restrict__ W) { tr_body(W, g_b2q, OUTDn, NPADn); }
__global__ void tr_o_kernel(const float* __restrict__ W) { tr_body(W, g_b2o, HIDn, HIDn); }

// ---------------- RoPE ----------------
__global__ void rope_kernel(const float* __restrict__ cosp, const float* __restrict__ sinp) {
    int idx = blockIdx.x * blockDim.x + threadIdx.x;
    const int total = Tn * (Hn + HKVn) * Dn;
    if (idx >= total) return;
    const int d = idx & 63;
    int rest = idx >> 6;
    const int h = rest % (Hn + HKVn);
    const int t = rest / (Hn + HKVn);
    const float c = cosp[t * Dn + d];
    const float s = sinp[t * Dn + d];
    if (h < Hn) {
        const float* row = g_qkvw + (size_t)t * OUTDn + h * Dn;
        float x = row[d];
        float rot = (d < 32) ? -row[d + 32] : row[d - 32];
        g_q[((size_t)t * Hn + h) * Dn + d] = x * c + rot * s;
    } else {
        const int g = h - Hn;
        const float* row = g_qkvw + (size_t)t * OUTDn + KOFF + g * Dn;
        float x = row[d];
        float rot = (d < 32) ? -row[d + 32] : row[d - 32];
        g_k[((size_t)t * HKVn + g) * Dn + d] = x * c + rot * s;
    }
}

// ---------------- mean-pool ----------------
__global__ void pool_kernel() {
    int idx = blockIdx.x * blockDim.x + threadIdx.x;
    if (idx >= NBn * Gn * Dn) return;
    const int d = idx & 63;
    int rest = idx >> 6;
    const int g = rest % Gn;
    const int n = rest / Gn;
    float sk = 0.f, sv = 0.f;
    #pragma unroll 4
    for (int b = 0; b < BLKn; b++) {
        const int t = n * BLKn + b;
        sk += g_k[((size_t)t * HKVn + g) * Dn + d];
        sv += g_qkvw[(size_t)t * OUTDn + VOFF + g * Dn + d];
    }
    g_kcmp[idx] = sk * (1.f / BLKn);
    g_vcmp[idx] = sv * (1.f / BLKn);
}

// ---------------- compressed attention: CTA per (t,g), warp per head ----------------
__global__ __launch_bounds__(512) void cmp2_kernel() {
    const int t = blockIdx.x, g = blockIdx.y;
    const int tid = threadIdx.x, w = tid >> 5, lane = tid & 31;
    __shared__ float kc[NBn][65], vc[NBn][65], qs[HGn][Dn], ps[HGn][NBn];

    for (int i = tid; i < NBn * Dn; i += 512) {
        int n = i >> 6, d = i & 63;
        kc[n][d] = g_kcmp[((size_t)n * Gn + g) * Dn + d];
        vc[n][d] = g_vcmp[((size_t)n * Gn + g) * Dn + d];
    }
    for (int i = tid; i < HGn * Dn; i += 512) {
        int hg = i >> 6, d = i & 63;
        qs[hg][d] = g_q[((size_t)t * Hn + g * HGn + hg) * Dn + d];
    }
    __syncthreads();

    const int nvis = (t + 1) >> 5;
    float sc[2];
    #pragma unroll
    for (int ii = 0; ii < 2; ii++) {
        const int n = lane + ii * 32;
        float s = NEGf;
        if (n < nvis) {
            float acc = 0.f;
            #pragma unroll
            for (int d = 0; d < Dn; d++) acc = fmaf(qs[w][d], kc[n][d], acc);
            s = acc * SCALEf;
        }
        sc[ii] = s;
    }
    float p0 = 0.f, p1 = 0.f;
    if (nvis > 0) {
        float m = warpMax(fmaxf(sc[0], sc[1]));
        float e0 = expf(sc[0] - m), e1 = expf(sc[1] - m);
        float inv = 1.f / warpSum(e0 + e1);
        p0 = e0 * inv; p1 = e1 * inv;
    }
    ps[w][lane] = p0; ps[w][lane + 32] = p1;
    float* pout = g_pcmp + ((size_t)t * Hn + g * HGn + w) * NBn;
    pout[lane] = p0; pout[lane + 32] = p1;
    __syncwarp();

    float a0 = 0.f, a1 = 0.f;
    for (int n = 0; n < nvis; n++) {
        const float p = ps[w][n];
        a0 = fmaf(p, vc[n][lane], a0);
        a1 = fmaf(p, vc[n][lane + 32], a1);
    }
    float* orow = g_ocmp + ((size_t)t * Hn + g * HGn + w) * Dn;
    orow[lane] = a0; orow[lane + 32] = a1;
}

// ---------------- top-8 ----------------
__global__ void topk_kernel() {
    int idx = blockIdx.x * blockDim.x + threadIdx.x;
    if (idx >= Tn * Gn) return;
    const int g = idx % Gn, t = idx / Gn, tb = t >> 5;
    float imp[NBn];
    for (int n = 0; n < NBn; n++) {
        if (n > tb) { imp[n] = NEGf; continue; }
        float s = 0.f;
        #pragma unroll
        for (int hg = 0; hg < HGn; hg++)
            s += g_pcmp[((size_t)t * Hn + g * HGn + hg) * NBn + n];
        if (n == 0)  s += 1e4f;
        if (n == tb) s += 1e4f;
        imp[n] = s;
    }
    int* sel = g_selidx + ((size_t)t * Gn + g) * NSELn;
    for (int i = 0; i < NSELn; i++) {
        int best = 0; float bv = imp[0];
        for (int n = 1; n < NBn; n++)
            if (imp[n] > bv) { bv = imp[n]; best = n; }
        sel[i] = best;
        imp[best] = -2e30f;
    }
}

// ---------------- selection attention: CTA per (t,g) ----------------
__global__ __launch_bounds__(512) void sel2_kernel() {
    const int t = blockIdx.x, g = blockIdx.y;
    const int tid = threadIdx.x, w = tid >> 5, lane = tid & 31;
    __shared__ float kb[BLKn][65], qs[HGn][Dn], ps[HGn][NSELn * BLKn];
    __shared__ int sel[NSELn];

    for (int i = tid; i < HGn * Dn; i += 512) {
        int hg = i >> 6, d = i & 63;
        qs[hg][d] = g_q[((size_t)t * Hn + g * HGn + hg) * Dn + d];
    }
    if (tid < NSELn) sel[tid] = g_selidx[((size_t)t * Gn + g) * NSELn + tid];
    __syncthreads();

    float sc[NSELn];
    for (int i = 0; i < NSELn; i++) {
        const int base = sel[i] * BLKn;
        for (int j = tid; j < BLKn * Dn; j += 512) {
            int b = j >> 6, d = j & 63;
            kb[b][d] = g_k[((size_t)(base + b) * HKVn + g) * Dn + d];
        }
        __syncthreads();
        const int pos = base + lane;
        float s = NEGf;
        if (pos <= t) {
            float acc = 0.f;
            #pragma unroll
            for (int d = 0; d < Dn; d++) acc = fmaf(qs[w][d], kb[lane][d], acc);
            s = acc * SCALEf;
        }
        sc[i] = s;
        __syncthreads();
    }
    float lm = sc[0];
    #pragma unroll
    for (int i = 1; i < NSELn; i++) lm = fmaxf(lm, sc[i]);
    float m = warpMax(lm);
    float lsum = 0.f, ev[NSELn];
    #pragma unroll
    for (int i = 0; i < NSELn; i++) { ev[i] = expf(sc[i] - m); lsum += ev[i]; }
    float inv = 1.f / warpSum(lsum);
    #pragma unroll
    for (int i = 0; i < NSELn; i++) ps[w][i * 32 + lane] = ev[i] * inv;
    __syncwarp();

    float a0 = 0.f, a1 = 0.f;
    for (int i = 0; i < NSELn; i++) {
        const int base = sel[i] * BLKn;
        for (int j = tid; j < BLKn * Dn; j += 512) {
            int b = j >> 6, d = j & 63;
            kb[b][d] = g_qkvw[(size_t)(base + b) * OUTDn + VOFF + g * Dn + d];
        }
        __syncthreads();
        if (base <= t) {
            for (int b = 0; b < BLKn; b++) {
                const float p = ps[w][i * 32 + b];
                a0 = fmaf(p, kb[b][lane], a0);
                a1 = fmaf(p, kb[b][lane + 32], a1);
            }
        }
        __syncthreads();
    }
    float* orow = g_osel + ((size_t)t * Hn + g * HGn + w) * Dn;
    orow[lane] = a0; orow[lane + 32] = a1;
}

// ---------------- sliding window: CTA per (t,g) ----------------
__global__ __launch_bounds__(512) void win2_kernel() {
    const int t = blockIdx.x, g = blockIdx.y;
    const int tid = threadIdx.x, w = tid >> 5, lane = tid & 31;
    __shared__ float kb[BLKn][65], qs[HGn][Dn], ps[HGn][WINn];

    for (int i = tid; i < HGn * Dn; i += 512) {
        int hg = i >> 6, d = i & 63;
        qs[hg][d] = g_q[((size_t)t * Hn + g * HGn + hg) * Dn + d];
    }
    __syncthreads();

    const int p0 = t - (WINn - 1);
    float sc[8];
    for (int i = 0; i < 8; i++) {
        const int base = p0 + i * 32;
        for (int j = tid; j < BLKn * Dn; j += 512) {
            int b = j >> 6, d = j & 63;
            int row = base + b; if (row < 0) row = 0;
            kb[b][d] = g_k[((size_t)row * HKVn + g) * Dn + d];
        }
        __syncthreads();
        const int pos = base + lane;
        float s = NEGf;
        if (pos >= 0) {
            float acc = 0.f;
            #pragma unroll
            for (int d = 0; d < Dn; d++) acc = fmaf(qs[w][d], kb[lane][d], acc);
            s = acc * SCALEf;
        }
        sc[i] = s;
        __syncthreads();
    }
    float lm = sc[0];
    #pragma unroll
    for (int i = 1; i < 8; i++) lm = fmaxf(lm, sc[i]);
    float m = warpMax(lm);
    float lsum = 0.f, ev[8];
    #pragma unroll
    for (int i = 0; i < 8; i++) { ev[i] = expf(sc[i] - m); lsum += ev[i]; }
    float inv = 1.f / warpSum(lsum);
    #pragma unroll
    for (int i = 0; i < 8; i++) ps[w][i * 32 + lane] = ev[i] * inv;
    __syncwarp();

    float a0 = 0.f, a1 = 0.f;
    for (int i = 0; i < 8; i++) {
        const int base = p0 + i * 32;
        for (int j = tid; j < BLKn * Dn; j += 512) {
            int b = j >> 6, d = j & 63;
            int row = base + b; if (row < 0) row = 0;
            kb[b][d] = g_qkvw[(size_t)row * OUTDn + VOFF + g * Dn + d];
        }
        __syncthreads();
        for (int b = 0; b < BLKn; b++) {
            const float p = ps[w][i * 32 + b];
            a0 = fmaf(p, kb[b][lane], a0);
            a1 = fmaf(p, kb[b][lane + 32], a1);
        }
        __syncthreads();
    }
    float* orow = g_owin + ((size_t)t * Hn + g * HGn + w) * Dn;
    orow[lane] = a0; orow[lane + 32] = a1;
}

// ---------------- gated combine -> 3-term split A operand ----------------
__global__ void combine_kernel() {
    int idx = blockIdx.x * blockDim.x + threadIdx.x;
    if (idx >= Tn * Hn * Dn) return;
    const int d = idx & 63;
    int rest = idx >> 6;
    const int h = rest % Hn;
    const int t = rest / Hn;
    const float* wrow = g_qkvw + (size_t)t * OUTDn + WOFF + h * 3;
    const float g0 = 1.f / (1.f + expf(-wrow[0]));
    const float g1 = 1.f / (1.f + expf(-wrow[1]));
    const float g2 = 1.f / (1.f + expf(-wrow[2]));
    float val = g0 * g_ocmp[idx] + g1 * g_osel[idx] + g2 * g_owin[idx];
    unsigned short hh, ll;
    f32_hl(val, hh, ll);
    unsigned short* p = (unsigned short*)g_a2o + (size_t)idx * 3;
    p[0] = hh; p[1] = hh; p[2] = ll;
}

// ---------------- launch ----------------
extern "C" void kernel_launch(void* const* d_in, const int* in_sizes, int n_in,
                              void* d_out, int out_size) {
    const float* x    = (const float*)d_in[0];
    const float* cosp = (const float*)d_in[1];
    const float* sinp = (const float*)d_in[2];
    const float* Wqkv = (const float*)d_in[3];
    const float* Wo   = (const float*)d_in[4];
    float* out = (float*)d_out;

    // opt-in to >48KB dynamic smem for the GEMMs (attribute set, not an allocation)
    cudaFuncSetAttribute(gemm_mma_qkvw, cudaFuncAttributeMaxDynamicSharedMemorySize, GEMM_SMEM);
    cudaFuncSetAttribute(gemm_mma_out,  cudaFuncAttributeMaxDynamicSharedMemorySize, GEMM_SMEM);

    conv_x_kernel<<<(Tn * HIDn + 255) / 256, 256>>>(x);
    {
        dim3 b(32, 32);
        tr_q_kernel<<<dim3(76, 64), b>>>(Wqkv);
        tr_o_kernel<<<dim3(64, 64), b>>>(Wo);
    }
    gemm_mma_qkvw<<<dim3(NPADn / 128, Tn / 128), 256, GEMM_SMEM>>>();
    rope_kernel<<<(Tn * (Hn + HKVn) * Dn + 255) / 256, 256>>>(cosp, sinp);
    pool_kernel<<<(NBn * Gn * Dn + 255) / 256, 256>>>();
    cmp2_kernel<<<dim3(Tn, Gn), 512>>>();
    topk_kernel<<<(Tn * Gn + 255) / 256, 256>>>();
    sel2_kernel<<<dim3(Tn, Gn), 512>>>();
    win2_kernel<<<dim3(Tn, Gn), 512>>>();
    combine_kernel<<<(Tn * Hn * Dn + 255) / 256, 256>>>();
    gemm_mma_out<<<dim3(HIDn / 128, Tn / 128), 256, GEMM_SMEM>>>(out);
}